// round 1
// baseline (speedup 1.0000x reference)
#include <cuda_runtime.h>
#include <math.h>

// ---------------- problem constants ----------------
#define BATCH      2
#define LSEQ       2048
#define NTOK       (BATCH*LSEQ)      // 4096
#define INPUT_DIM  512
#define DMODEL     1024
#define NHEAD      16
#define HD         64
#define MLPH       4096
#define LN_EPS     1e-5f

// ---------------- scratch (static device, no allocs) ----------------
__device__ float g_h  [NTOK*DMODEL];
__device__ float g_hn [NTOK*DMODEL];
__device__ float g_kq [NTOK*2*DMODEL];
__device__ float g_v  [NTOK*DMODEL];
__device__ float g_o  [NTOK*DMODEL];
__device__ float g_xo [NTOK*DMODEL];
__device__ float g_mlp[NTOK*MLPH];

// ---------------- SGEMM: C = A[MxK] @ B[KxN] + epilogue ----------------
// BM=BN=128, BK=8, 256 threads, each thread 8x8 microtile.
#define BM 128
#define BN 128
#define BK 8
#define TM 8
#define TN 8

enum { EPI_BIAS = 0, EPI_EMBED = 1, EPI_RES = 2, EPI_GELU = 3 };

template <int EPI>
__global__ __launch_bounds__(256)
void sgemm_kernel(int M, int N, int K,
                  const float* __restrict__ A,
                  const float* __restrict__ B,
                  const float* __restrict__ bias,
                  const float* __restrict__ extra,   // wpe (EMBED) or residual (RES)
                  float* __restrict__ C)
{
    __shared__ float As[BK][BM];
    __shared__ float Bs[BK][BN];

    const int tid = threadIdx.x;
    const int bm  = blockIdx.y;
    const int bn  = blockIdx.x;

    const int threadRow = tid >> 4;      // 0..15
    const int threadCol = tid & 15;      // 0..15

    // A tile loader: 128 rows x 8 cols, one float4 per thread
    const int aRow = tid >> 1;           // 0..127
    const int aCol = (tid & 1) << 2;     // 0 or 4
    // B tile loader: 8 rows x 128 cols, one float4 per thread
    const int bRow = tid >> 5;           // 0..7
    const int bCol = (tid & 31) << 2;    // 0..124

    const float* Aptr = A + (size_t)(bm * BM + aRow) * K + aCol;
    const float* Bptr = B + (size_t)bRow * N + bn * BN + bCol;

    float acc[TM][TN];
#pragma unroll
    for (int i = 0; i < TM; i++)
#pragma unroll
        for (int j = 0; j < TN; j++) acc[i][j] = 0.f;

    for (int k0 = 0; k0 < K; k0 += BK) {
        float4 a4 = *reinterpret_cast<const float4*>(Aptr + k0);
        As[aCol + 0][aRow] = a4.x;
        As[aCol + 1][aRow] = a4.y;
        As[aCol + 2][aRow] = a4.z;
        As[aCol + 3][aRow] = a4.w;
        float4 b4 = *reinterpret_cast<const float4*>(Bptr + (size_t)k0 * N);
        *reinterpret_cast<float4*>(&Bs[bRow][bCol]) = b4;
        __syncthreads();

#pragma unroll
        for (int k = 0; k < BK; k++) {
            float4 a0 = *reinterpret_cast<const float4*>(&As[k][threadRow * TM]);
            float4 a1 = *reinterpret_cast<const float4*>(&As[k][threadRow * TM + 4]);
            float4 b0 = *reinterpret_cast<const float4*>(&Bs[k][threadCol * TN]);
            float4 b1 = *reinterpret_cast<const float4*>(&Bs[k][threadCol * TN + 4]);
            float rm[TM] = {a0.x, a0.y, a0.z, a0.w, a1.x, a1.y, a1.z, a1.w};
            float rn[TN] = {b0.x, b0.y, b0.z, b0.w, b1.x, b1.y, b1.z, b1.w};
#pragma unroll
            for (int i = 0; i < TM; i++)
#pragma unroll
                for (int j = 0; j < TN; j++)
                    acc[i][j] = fmaf(rm[i], rn[j], acc[i][j]);
        }
        __syncthreads();
    }

    // epilogue, float4 stores
#pragma unroll
    for (int i = 0; i < TM; i++) {
        const int row = bm * BM + threadRow * TM + i;
        const float* eptr = nullptr;
        if (EPI == EPI_EMBED) eptr = extra + (size_t)(row & (LSEQ - 1)) * N;
        if (EPI == EPI_RES)   eptr = extra + (size_t)row * N;
#pragma unroll
        for (int j = 0; j < TN; j += 4) {
            const int col = bn * BN + threadCol * TN + j;
            float v[4];
#pragma unroll
            for (int q = 0; q < 4; q++) {
                float t = acc[i][j + q] + bias[col + q];
                if (EPI == EPI_EMBED) t += eptr[col + q];
                if (EPI == EPI_RES)   t += eptr[col + q];
                if (EPI == EPI_GELU)  t = 0.5f * t * (1.f + erff(t * 0.70710678118654752f));
                v[q] = t;
            }
            *reinterpret_cast<float4*>(C + (size_t)row * N + col) =
                make_float4(v[0], v[1], v[2], v[3]);
        }
    }
}

// ---------------- LayerNorm: one block per row of 1024 ----------------
__global__ __launch_bounds__(256)
void ln_kernel(const float* __restrict__ x,
               const float* __restrict__ w,
               const float* __restrict__ b,
               float* __restrict__ y)
{
    const int row = blockIdx.x;
    const int c = threadIdx.x * 4;
    const float* xr = x + (size_t)row * DMODEL;
    float4 v = *reinterpret_cast<const float4*>(xr + c);
    float s  = v.x + v.y + v.z + v.w;
    float sq = v.x * v.x + v.y * v.y + v.z * v.z + v.w * v.w;
#pragma unroll
    for (int off = 16; off; off >>= 1) {
        s  += __shfl_xor_sync(0xffffffffu, s,  off);
        sq += __shfl_xor_sync(0xffffffffu, sq, off);
    }
    __shared__ float ss[8], ssq[8];
    const int warp = threadIdx.x >> 5, lane = threadIdx.x & 31;
    if (lane == 0) { ss[warp] = s; ssq[warp] = sq; }
    __syncthreads();
    float tot = 0.f, totq = 0.f;
#pragma unroll
    for (int i = 0; i < 8; i++) { tot += ss[i]; totq += ssq[i]; }
    const float mu  = tot * (1.f / DMODEL);
    const float var = totq * (1.f / DMODEL) - mu * mu;
    const float inv = rsqrtf(var + LN_EPS);
    float4 wv = *reinterpret_cast<const float4*>(w + c);
    float4 bv = *reinterpret_cast<const float4*>(b + c);
    float4 out;
    out.x = (v.x - mu) * inv * wv.x + bv.x;
    out.y = (v.y - mu) * inv * wv.y + bv.y;
    out.z = (v.z - mu) * inv * wv.z + bv.z;
    out.w = (v.w - mu) * inv * wv.w + bv.w;
    *reinterpret_cast<float4*>(y + (size_t)row * DMODEL + c) = out;
}

// ---------------- Flash attention (causal, fp32) ----------------
// grid: (L/64, B*NHEAD); 256 threads; 64x64 tiles; hd = 64.
#define ATT_PAD   68
#define ATT_SMEM  (4 * 64 * ATT_PAD * 4)   // Qt, Kt, Vs, Ps

__global__ __launch_bounds__(256)
void attn_kernel(const float* __restrict__ kq,
                 const float* __restrict__ vbuf,
                 float* __restrict__ obuf)
{
    extern __shared__ float sm[];
    float* Qt = sm;                    // [d][row], scaled q
    float* Kt = sm + 64 * ATT_PAD;     // [d][row]
    float* Vs = sm + 2 * 64 * ATT_PAD; // [row][d]
    float* Ps = sm + 3 * 64 * ATT_PAD; // [row][col]

    const int tid   = threadIdx.x;
    const int qtile = blockIdx.x;
    const int bh    = blockIdx.y;
    const int bidx  = bh >> 4, h = bh & 15;
    const int rowbase = bidx * LSEQ;
    const int q0 = qtile * 64;
    const int tr = tid >> 4, tc = tid & 15;   // 4-row x 4-col microtile

    // load Q transposed (scaled by 1/sqrt(hd))
#pragma unroll
    for (int it = 0; it < 4; it++) {
        int idx = tid + it * 256;
        int r = idx >> 4;
        int d4 = (idx & 15) << 2;
        const float* p = kq + (size_t)(rowbase + q0 + r) * (2 * DMODEL) + DMODEL + h * HD + d4;
        float4 qv = *reinterpret_cast<const float4*>(p);
        Qt[(d4 + 0) * ATT_PAD + r] = qv.x * 0.125f;
        Qt[(d4 + 1) * ATT_PAD + r] = qv.y * 0.125f;
        Qt[(d4 + 2) * ATT_PAD + r] = qv.z * 0.125f;
        Qt[(d4 + 3) * ATT_PAD + r] = qv.w * 0.125f;
    }

    float m[4], l[4], o[4][4];
#pragma unroll
    for (int a = 0; a < 4; a++) {
        m[a] = -INFINITY; l[a] = 0.f;
#pragma unroll
        for (int c2 = 0; c2 < 4; c2++) o[a][c2] = 0.f;
    }

    for (int jt = 0; jt <= qtile; jt++) {
        __syncthreads();  // previous iter's PV done; also covers initial Q load
        const int n0 = jt * 64;
#pragma unroll
        for (int it = 0; it < 4; it++) {
            int idx = tid + it * 256;
            int r = idx >> 4;
            int d4 = (idx & 15) << 2;
            const float* kp = kq + (size_t)(rowbase + n0 + r) * (2 * DMODEL) + h * HD + d4;
            float4 kv = *reinterpret_cast<const float4*>(kp);
            Kt[(d4 + 0) * ATT_PAD + r] = kv.x;
            Kt[(d4 + 1) * ATT_PAD + r] = kv.y;
            Kt[(d4 + 2) * ATT_PAD + r] = kv.z;
            Kt[(d4 + 3) * ATT_PAD + r] = kv.w;
            const float* vp = vbuf + (size_t)(rowbase + n0 + r) * DMODEL + h * HD + d4;
            *reinterpret_cast<float4*>(&Vs[r * ATT_PAD + d4]) =
                *reinterpret_cast<const float4*>(vp);
        }
        __syncthreads();

        float s[4][4];
#pragma unroll
        for (int a = 0; a < 4; a++)
#pragma unroll
            for (int c2 = 0; c2 < 4; c2++) s[a][c2] = 0.f;

#pragma unroll 4
        for (int d = 0; d < 64; d++) {
            float4 qa = *reinterpret_cast<const float4*>(&Qt[d * ATT_PAD + 4 * tr]);
            float4 kb = *reinterpret_cast<const float4*>(&Kt[d * ATT_PAD + 4 * tc]);
            s[0][0] = fmaf(qa.x, kb.x, s[0][0]); s[0][1] = fmaf(qa.x, kb.y, s[0][1]);
            s[0][2] = fmaf(qa.x, kb.z, s[0][2]); s[0][3] = fmaf(qa.x, kb.w, s[0][3]);
            s[1][0] = fmaf(qa.y, kb.x, s[1][0]); s[1][1] = fmaf(qa.y, kb.y, s[1][1]);
            s[1][2] = fmaf(qa.y, kb.z, s[1][2]); s[1][3] = fmaf(qa.y, kb.w, s[1][3]);
            s[2][0] = fmaf(qa.z, kb.x, s[2][0]); s[2][1] = fmaf(qa.z, kb.y, s[2][1]);
            s[2][2] = fmaf(qa.z, kb.z, s[2][2]); s[2][3] = fmaf(qa.z, kb.w, s[2][3]);
            s[3][0] = fmaf(qa.w, kb.x, s[3][0]); s[3][1] = fmaf(qa.w, kb.y, s[3][1]);
            s[3][2] = fmaf(qa.w, kb.z, s[3][2]); s[3][3] = fmaf(qa.w, kb.w, s[3][3]);
        }

        if (jt == qtile) {  // causal mask on diagonal tile
#pragma unroll
            for (int a = 0; a < 4; a++)
#pragma unroll
                for (int c2 = 0; c2 < 4; c2++)
                    if (4 * tc + c2 > 4 * tr + a) s[a][c2] = -INFINITY;
        }

        // online softmax (row groups = 16 lanes sharing tr)
#pragma unroll
        for (int a = 0; a < 4; a++) {
            float mx = fmaxf(fmaxf(s[a][0], s[a][1]), fmaxf(s[a][2], s[a][3]));
#pragma unroll
            for (int off = 1; off < 16; off <<= 1)
                mx = fmaxf(mx, __shfl_xor_sync(0xffffffffu, mx, off));
            const float nm = fmaxf(m[a], mx);
            const float corr = expf(m[a] - nm);
            float rs = 0.f;
#pragma unroll
            for (int c2 = 0; c2 < 4; c2++) { s[a][c2] = expf(s[a][c2] - nm); rs += s[a][c2]; }
#pragma unroll
            for (int off = 1; off < 16; off <<= 1)
                rs += __shfl_xor_sync(0xffffffffu, rs, off);
            l[a] = l[a] * corr + rs;
            m[a] = nm;
#pragma unroll
            for (int c2 = 0; c2 < 4; c2++) o[a][c2] *= corr;
            *reinterpret_cast<float4*>(&Ps[(4 * tr + a) * ATT_PAD + 4 * tc]) =
                make_float4(s[a][0], s[a][1], s[a][2], s[a][3]);
        }
        __syncthreads();

        // O += P @ V
#pragma unroll 4
        for (int j = 0; j < 64; j++) {
            float4 vb = *reinterpret_cast<const float4*>(&Vs[j * ATT_PAD + 4 * tc]);
            float p0 = Ps[(4 * tr + 0) * ATT_PAD + j];
            float p1 = Ps[(4 * tr + 1) * ATT_PAD + j];
            float p2 = Ps[(4 * tr + 2) * ATT_PAD + j];
            float p3 = Ps[(4 * tr + 3) * ATT_PAD + j];
            o[0][0] = fmaf(p0, vb.x, o[0][0]); o[0][1] = fmaf(p0, vb.y, o[0][1]);
            o[0][2] = fmaf(p0, vb.z, o[0][2]); o[0][3] = fmaf(p0, vb.w, o[0][3]);
            o[1][0] = fmaf(p1, vb.x, o[1][0]); o[1][1] = fmaf(p1, vb.y, o[1][1]);
            o[1][2] = fmaf(p1, vb.z, o[1][2]); o[1][3] = fmaf(p1, vb.w, o[1][3]);
            o[2][0] = fmaf(p2, vb.x, o[2][0]); o[2][1] = fmaf(p2, vb.y, o[2][1]);
            o[2][2] = fmaf(p2, vb.z, o[2][2]); o[2][3] = fmaf(p2, vb.w, o[2][3]);
            o[3][0] = fmaf(p3, vb.x, o[3][0]); o[3][1] = fmaf(p3, vb.y, o[3][1]);
            o[3][2] = fmaf(p3, vb.z, o[3][2]); o[3][3] = fmaf(p3, vb.w, o[3][3]);
        }
    }

#pragma unroll
    for (int a = 0; a < 4; a++) {
        const float inv = 1.f / l[a];
        float4 ov = make_float4(o[a][0] * inv, o[a][1] * inv, o[a][2] * inv, o[a][3] * inv);
        *reinterpret_cast<float4*>(
            obuf + (size_t)(rowbase + q0 + 4 * tr + a) * DMODEL + h * HD + 4 * tc) = ov;
    }
}

// ---------------- launch ----------------
extern "C" void kernel_launch(void* const* d_in, const int* in_sizes, int n_in,
                              void* d_out, int out_size)
{
    const float* x      = (const float*)d_in[0];
    const float* wte_w  = (const float*)d_in[1];
    const float* wte_b  = (const float*)d_in[2];
    const float* wpe    = (const float*)d_in[3];
    const float* ln1_w  = (const float*)d_in[4];
    const float* ln1_b  = (const float*)d_in[5];
    const float* kq_w   = (const float*)d_in[6];
    const float* kq_b   = (const float*)d_in[7];
    const float* v_w    = (const float*)d_in[8];
    const float* v_b    = (const float*)d_in[9];
    const float* ao_w   = (const float*)d_in[10];
    const float* ao_b   = (const float*)d_in[11];
    const float* ln2_w  = (const float*)d_in[12];
    const float* ln2_b  = (const float*)d_in[13];
    const float* fc_w   = (const float*)d_in[14];
    const float* fc_b   = (const float*)d_in[15];
    const float* proj_w = (const float*)d_in[16];
    const float* proj_b = (const float*)d_in[17];

    float *h, *hn, *kqb, *vb, *ob, *xo, *mlp;
    cudaGetSymbolAddress((void**)&h,   g_h);
    cudaGetSymbolAddress((void**)&hn,  g_hn);
    cudaGetSymbolAddress((void**)&kqb, g_kq);
    cudaGetSymbolAddress((void**)&vb,  g_v);
    cudaGetSymbolAddress((void**)&ob,  g_o);
    cudaGetSymbolAddress((void**)&xo,  g_xo);
    cudaGetSymbolAddress((void**)&mlp, g_mlp);

    float* out0     = (float*)d_out;                       // [4096, 512]
    float* attn_out = out0 + (size_t)NTOK * INPUT_DIM;     // [4096, 1024]

    cudaFuncSetAttribute(attn_kernel, cudaFuncAttributeMaxDynamicSharedMemorySize, ATT_SMEM);

    // 1. h = x @ wte_w + wte_b + wpe
    sgemm_kernel<EPI_EMBED><<<dim3(DMODEL / BN, NTOK / BM), 256>>>(
        NTOK, DMODEL, INPUT_DIM, x, wte_w, wte_b, wpe, h);
    // 2. hn = LN1(h)
    ln_kernel<<<NTOK, 256>>>(h, ln1_w, ln1_b, hn);
    // 3. kq = hn @ kq_w + kq_b
    sgemm_kernel<EPI_BIAS><<<dim3(2 * DMODEL / BN, NTOK / BM), 256>>>(
        NTOK, 2 * DMODEL, DMODEL, hn, kq_w, kq_b, nullptr, kqb);
    // 4. v = hn @ v_w + v_b
    sgemm_kernel<EPI_BIAS><<<dim3(DMODEL / BN, NTOK / BM), 256>>>(
        NTOK, DMODEL, DMODEL, hn, v_w, v_b, nullptr, vb);
    // 5. attention
    attn_kernel<<<dim3(LSEQ / 64, BATCH * NHEAD), 256, ATT_SMEM>>>(kqb, vb, ob);
    // 6. attn_out = hn + (o @ ao_w + ao_b)
    sgemm_kernel<EPI_RES><<<dim3(DMODEL / BN, NTOK / BM), 256>>>(
        NTOK, DMODEL, DMODEL, ob, ao_w, ao_b, hn, attn_out);
    // 7. xo = LN2(attn_out)
    ln_kernel<<<NTOK, 256>>>(attn_out, ln2_w, ln2_b, xo);
    // 8. mlp = gelu(xo @ fc_w + fc_b)
    sgemm_kernel<EPI_GELU><<<dim3(MLPH / BN, NTOK / BM), 256>>>(
        NTOK, MLPH, DMODEL, xo, fc_w, fc_b, nullptr, mlp);
    // 9. out = mlp @ proj_w + proj_b
    sgemm_kernel<EPI_BIAS><<<dim3(INPUT_DIM / BN, NTOK / BM), 256>>>(
        NTOK, INPUT_DIM, MLPH, mlp, proj_w, proj_b, nullptr, out0);
}

// round 2
// speedup vs baseline: 1.0054x; 1.0054x over previous
#include <cuda_runtime.h>
#include <math.h>

// ---------------- problem constants ----------------
#define BATCH      2
#define LSEQ       2048
#define NTOK       (BATCH*LSEQ)      // 4096
#define INPUT_DIM  512
#define DMODEL     1024
#define NHEAD      16
#define HD         64
#define MLPH       4096
#define LN_EPS     1e-5f

// ---------------- scratch (static device, no allocs) ----------------
__device__ float g_h  [NTOK*DMODEL];
__device__ float g_hn [NTOK*DMODEL];
__device__ float g_kq [NTOK*2*DMODEL];
__device__ float g_v  [NTOK*DMODEL];
__device__ float g_o  [NTOK*DMODEL];
__device__ float g_xo [NTOK*DMODEL];
__device__ float g_mlp[NTOK*MLPH];

// ---------------- SGEMM: C = A[MxK] @ B[KxN] + epilogue ----------------
// BM=BN=128, BK=8, 256 threads, each thread 8x8 microtile.
#define BM 128
#define BN 128
#define BK 8
#define TM 8
#define TN 8

enum { EPI_BIAS = 0, EPI_EMBED = 1, EPI_RES = 2, EPI_GELU = 3 };

template <int EPI>
__global__ __launch_bounds__(256)
void sgemm_kernel(int M, int N, int K,
                  const float* __restrict__ A,
                  const float* __restrict__ B,
                  const float* __restrict__ bias,
                  const float* __restrict__ extra,   // wpe (EMBED) or residual (RES)
                  float* __restrict__ C)
{
    __shared__ float As[BK][BM];
    __shared__ float Bs[BK][BN];

    const int tid = threadIdx.x;
    const int bm  = blockIdx.y;
    const int bn  = blockIdx.x;

    const int threadRow = tid >> 4;      // 0..15
    const int threadCol = tid & 15;      // 0..15

    // A tile loader: 128 rows x 8 cols, one float4 per thread
    const int aRow = tid >> 1;           // 0..127
    const int aCol = (tid & 1) << 2;     // 0 or 4
    // B tile loader: 8 rows x 128 cols, one float4 per thread
    const int bRow = tid >> 5;           // 0..7
    const int bCol = (tid & 31) << 2;    // 0..124

    const float* Aptr = A + (size_t)(bm * BM + aRow) * K + aCol;
    const float* Bptr = B + (size_t)bRow * N + bn * BN + bCol;

    float acc[TM][TN];
#pragma unroll
    for (int i = 0; i < TM; i++)
#pragma unroll
        for (int j = 0; j < TN; j++) acc[i][j] = 0.f;

    for (int k0 = 0; k0 < K; k0 += BK) {
        float4 a4 = *reinterpret_cast<const float4*>(Aptr + k0);
        As[aCol + 0][aRow] = a4.x;
        As[aCol + 1][aRow] = a4.y;
        As[aCol + 2][aRow] = a4.z;
        As[aCol + 3][aRow] = a4.w;
        float4 b4 = *reinterpret_cast<const float4*>(Bptr + (size_t)k0 * N);
        *reinterpret_cast<float4*>(&Bs[bRow][bCol]) = b4;
        __syncthreads();

#pragma unroll
        for (int k = 0; k < BK; k++) {
            float4 a0 = *reinterpret_cast<const float4*>(&As[k][threadRow * TM]);
            float4 a1 = *reinterpret_cast<const float4*>(&As[k][threadRow * TM + 4]);
            float4 b0 = *reinterpret_cast<const float4*>(&Bs[k][threadCol * TN]);
            float4 b1 = *reinterpret_cast<const float4*>(&Bs[k][threadCol * TN + 4]);
            float rm[TM] = {a0.x, a0.y, a0.z, a0.w, a1.x, a1.y, a1.z, a1.w};
            float rn[TN] = {b0.x, b0.y, b0.z, b0.w, b1.x, b1.y, b1.z, b1.w};
#pragma unroll
            for (int i = 0; i < TM; i++)
#pragma unroll
                for (int j = 0; j < TN; j++)
                    acc[i][j] = fmaf(rm[i], rn[j], acc[i][j]);
        }
        __syncthreads();
    }

    // epilogue, float4 stores
#pragma unroll
    for (int i = 0; i < TM; i++) {
        const int row = bm * BM + threadRow * TM + i;
        const float* eptr = nullptr;
        if (EPI == EPI_EMBED) eptr = extra + (size_t)(row & (LSEQ - 1)) * N;
        if (EPI == EPI_RES)   eptr = extra + (size_t)row * N;
#pragma unroll
        for (int j = 0; j < TN; j += 4) {
            const int col = bn * BN + threadCol * TN + j;
            float v[4];
#pragma unroll
            for (int q = 0; q < 4; q++) {
                float t = acc[i][j + q] + bias[col + q];
                if (EPI == EPI_EMBED) t += eptr[col + q];
                if (EPI == EPI_RES)   t += eptr[col + q];
                if (EPI == EPI_GELU)  t = 0.5f * t * (1.f + erff(t * 0.70710678118654752f));
                v[q] = t;
            }
            *reinterpret_cast<float4*>(C + (size_t)row * N + col) =
                make_float4(v[0], v[1], v[2], v[3]);
        }
    }
}

// ---------------- LayerNorm: one block per row of 1024 ----------------
__global__ __launch_bounds__(256)
void ln_kernel(const float* __restrict__ x,
               const float* __restrict__ w,
               const float* __restrict__ b,
               float* __restrict__ y)
{
    const int row = blockIdx.x;
    const int c = threadIdx.x * 4;
    const float* xr = x + (size_t)row * DMODEL;
    float4 v = *reinterpret_cast<const float4*>(xr + c);
    float s  = v.x + v.y + v.z + v.w;
    float sq = v.x * v.x + v.y * v.y + v.z * v.z + v.w * v.w;
#pragma unroll
    for (int off = 16; off; off >>= 1) {
        s  += __shfl_xor_sync(0xffffffffu, s,  off);
        sq += __shfl_xor_sync(0xffffffffu, sq, off);
    }
    __shared__ float ss[8], ssq[8];
    const int warp = threadIdx.x >> 5, lane = threadIdx.x & 31;
    if (lane == 0) { ss[warp] = s; ssq[warp] = sq; }
    __syncthreads();
    float tot = 0.f, totq = 0.f;
#pragma unroll
    for (int i = 0; i < 8; i++) { tot += ss[i]; totq += ssq[i]; }
    const float mu  = tot * (1.f / DMODEL);
    const float var = totq * (1.f / DMODEL) - mu * mu;
    const float inv = rsqrtf(var + LN_EPS);
    float4 wv = *reinterpret_cast<const float4*>(w + c);
    float4 bv = *reinterpret_cast<const float4*>(b + c);
    float4 out;
    out.x = (v.x - mu) * inv * wv.x + bv.x;
    out.y = (v.y - mu) * inv * wv.y + bv.y;
    out.z = (v.z - mu) * inv * wv.z + bv.z;
    out.w = (v.w - mu) * inv * wv.w + bv.w;
    *reinterpret_cast<float4*>(y + (size_t)row * DMODEL + c) = out;
}

// ---------------- Flash attention (causal, fp32) ----------------
// grid: (L/64, B*NHEAD); 256 threads; 64x64 tiles; hd = 64.
#define ATT_PAD   68
#define ATT_SMEM  (4 * 64 * ATT_PAD * 4)   // Qt, Kt, Vs, Ps

__global__ __launch_bounds__(256)
void attn_kernel(const float* __restrict__ kq,
                 const float* __restrict__ vbuf,
                 float* __restrict__ obuf)
{
    extern __shared__ float sm[];
    float* Qt = sm;                    // [d][row], scaled q
    float* Kt = sm + 64 * ATT_PAD;     // [d][row]
    float* Vs = sm + 2 * 64 * ATT_PAD; // [row][d]
    float* Ps = sm + 3 * 64 * ATT_PAD; // [row][col]

    const int tid   = threadIdx.x;
    const int qtile = blockIdx.x;
    const int bh    = blockIdx.y;
    const int bidx  = bh >> 4, h = bh & 15;
    const int rowbase = bidx * LSEQ;
    const int q0 = qtile * 64;
    const int tr = tid >> 4, tc = tid & 15;   // 4-row x 4-col microtile

    // load Q transposed (scaled by 1/sqrt(hd))
#pragma unroll
    for (int it = 0; it < 4; it++) {
        int idx = tid + it * 256;
        int r = idx >> 4;
        int d4 = (idx & 15) << 2;
        const float* p = kq + (size_t)(rowbase + q0 + r) * (2 * DMODEL) + DMODEL + h * HD + d4;
        float4 qv = *reinterpret_cast<const float4*>(p);
        Qt[(d4 + 0) * ATT_PAD + r] = qv.x * 0.125f;
        Qt[(d4 + 1) * ATT_PAD + r] = qv.y * 0.125f;
        Qt[(d4 + 2) * ATT_PAD + r] = qv.z * 0.125f;
        Qt[(d4 + 3) * ATT_PAD + r] = qv.w * 0.125f;
    }

    float m[4], l[4], o[4][4];
#pragma unroll
    for (int a = 0; a < 4; a++) {
        m[a] = -INFINITY; l[a] = 0.f;
#pragma unroll
        for (int c2 = 0; c2 < 4; c2++) o[a][c2] = 0.f;
    }

    for (int jt = 0; jt <= qtile; jt++) {
        __syncthreads();  // previous iter's PV done; also covers initial Q load
        const int n0 = jt * 64;
#pragma unroll
        for (int it = 0; it < 4; it++) {
            int idx = tid + it * 256;
            int r = idx >> 4;
            int d4 = (idx & 15) << 2;
            const float* kp = kq + (size_t)(rowbase + n0 + r) * (2 * DMODEL) + h * HD + d4;
            float4 kv = *reinterpret_cast<const float4*>(kp);
            Kt[(d4 + 0) * ATT_PAD + r] = kv.x;
            Kt[(d4 + 1) * ATT_PAD + r] = kv.y;
            Kt[(d4 + 2) * ATT_PAD + r] = kv.z;
            Kt[(d4 + 3) * ATT_PAD + r] = kv.w;
            const float* vp = vbuf + (size_t)(rowbase + n0 + r) * DMODEL + h * HD + d4;
            *reinterpret_cast<float4*>(&Vs[r * ATT_PAD + d4]) =
                *reinterpret_cast<const float4*>(vp);
        }
        __syncthreads();

        float s[4][4];
#pragma unroll
        for (int a = 0; a < 4; a++)
#pragma unroll
            for (int c2 = 0; c2 < 4; c2++) s[a][c2] = 0.f;

#pragma unroll 4
        for (int d = 0; d < 64; d++) {
            float4 qa = *reinterpret_cast<const float4*>(&Qt[d * ATT_PAD + 4 * tr]);
            float4 kb = *reinterpret_cast<const float4*>(&Kt[d * ATT_PAD + 4 * tc]);
            s[0][0] = fmaf(qa.x, kb.x, s[0][0]); s[0][1] = fmaf(qa.x, kb.y, s[0][1]);
            s[0][2] = fmaf(qa.x, kb.z, s[0][2]); s[0][3] = fmaf(qa.x, kb.w, s[0][3]);
            s[1][0] = fmaf(qa.y, kb.x, s[1][0]); s[1][1] = fmaf(qa.y, kb.y, s[1][1]);
            s[1][2] = fmaf(qa.y, kb.z, s[1][2]); s[1][3] = fmaf(qa.y, kb.w, s[1][3]);
            s[2][0] = fmaf(qa.z, kb.x, s[2][0]); s[2][1] = fmaf(qa.z, kb.y, s[2][1]);
            s[2][2] = fmaf(qa.z, kb.z, s[2][2]); s[2][3] = fmaf(qa.z, kb.w, s[2][3]);
            s[3][0] = fmaf(qa.w, kb.x, s[3][0]); s[3][1] = fmaf(qa.w, kb.y, s[3][1]);
            s[3][2] = fmaf(qa.w, kb.z, s[3][2]); s[3][3] = fmaf(qa.w, kb.w, s[3][3]);
        }

        if (jt == qtile) {  // causal mask on diagonal tile
#pragma unroll
            for (int a = 0; a < 4; a++)
#pragma unroll
                for (int c2 = 0; c2 < 4; c2++)
                    if (4 * tc + c2 > 4 * tr + a) s[a][c2] = -INFINITY;
        }

        // online softmax (row groups = 16 lanes sharing tr)
#pragma unroll
        for (int a = 0; a < 4; a++) {
            float mx = fmaxf(fmaxf(s[a][0], s[a][1]), fmaxf(s[a][2], s[a][3]));
#pragma unroll
            for (int off = 1; off < 16; off <<= 1)
                mx = fmaxf(mx, __shfl_xor_sync(0xffffffffu, mx, off));
            const float nm = fmaxf(m[a], mx);
            const float corr = expf(m[a] - nm);
            float rs = 0.f;
#pragma unroll
            for (int c2 = 0; c2 < 4; c2++) { s[a][c2] = expf(s[a][c2] - nm); rs += s[a][c2]; }
#pragma unroll
            for (int off = 1; off < 16; off <<= 1)
                rs += __shfl_xor_sync(0xffffffffu, rs, off);
            l[a] = l[a] * corr + rs;
            m[a] = nm;
#pragma unroll
            for (int c2 = 0; c2 < 4; c2++) o[a][c2] *= corr;
            *reinterpret_cast<float4*>(&Ps[(4 * tr + a) * ATT_PAD + 4 * tc]) =
                make_float4(s[a][0], s[a][1], s[a][2], s[a][3]);
        }
        __syncthreads();

        // O += P @ V
#pragma unroll 4
        for (int j = 0; j < 64; j++) {
            float4 vb = *reinterpret_cast<const float4*>(&Vs[j * ATT_PAD + 4 * tc]);
            float p0 = Ps[(4 * tr + 0) * ATT_PAD + j];
            float p1 = Ps[(4 * tr + 1) * ATT_PAD + j];
            float p2 = Ps[(4 * tr + 2) * ATT_PAD + j];
            float p3 = Ps[(4 * tr + 3) * ATT_PAD + j];
            o[0][0] = fmaf(p0, vb.x, o[0][0]); o[0][1] = fmaf(p0, vb.y, o[0][1]);
            o[0][2] = fmaf(p0, vb.z, o[0][2]); o[0][3] = fmaf(p0, vb.w, o[0][3]);
            o[1][0] = fmaf(p1, vb.x, o[1][0]); o[1][1] = fmaf(p1, vb.y, o[1][1]);
            o[1][2] = fmaf(p1, vb.z, o[1][2]); o[1][3] = fmaf(p1, vb.w, o[1][3]);
            o[2][0] = fmaf(p2, vb.x, o[2][0]); o[2][1] = fmaf(p2, vb.y, o[2][1]);
            o[2][2] = fmaf(p2, vb.z, o[2][2]); o[2][3] = fmaf(p2, vb.w, o[2][3]);
            o[3][0] = fmaf(p3, vb.x, o[3][0]); o[3][1] = fmaf(p3, vb.y, o[3][1]);
            o[3][2] = fmaf(p3, vb.z, o[3][2]); o[3][3] = fmaf(p3, vb.w, o[3][3]);
        }
    }

#pragma unroll
    for (int a = 0; a < 4; a++) {
        const float inv = 1.f / l[a];
        float4 ov = make_float4(o[a][0] * inv, o[a][1] * inv, o[a][2] * inv, o[a][3] * inv);
        *reinterpret_cast<float4*>(
            obuf + (size_t)(rowbase + q0 + 4 * tr + a) * DMODEL + h * HD + 4 * tc) = ov;
    }
}

// ---------------- launch ----------------
extern "C" void kernel_launch(void* const* d_in, const int* in_sizes, int n_in,
                              void* d_out, int out_size)
{
    const float* x      = (const float*)d_in[0];
    const float* wte_w  = (const float*)d_in[1];
    const float* wte_b  = (const float*)d_in[2];
    const float* wpe    = (const float*)d_in[3];
    const float* ln1_w  = (const float*)d_in[4];
    const float* ln1_b  = (const float*)d_in[5];
    const float* kq_w   = (const float*)d_in[6];
    const float* kq_b   = (const float*)d_in[7];
    const float* v_w    = (const float*)d_in[8];
    const float* v_b    = (const float*)d_in[9];
    const float* ao_w   = (const float*)d_in[10];
    const float* ao_b   = (const float*)d_in[11];
    const float* ln2_w  = (const float*)d_in[12];
    const float* ln2_b  = (const float*)d_in[13];
    const float* fc_w   = (const float*)d_in[14];
    const float* fc_b   = (const float*)d_in[15];
    const float* proj_w = (const float*)d_in[16];
    const float* proj_b = (const float*)d_in[17];

    float *h, *hn, *kqb, *vb, *ob, *xo, *mlp;
    cudaGetSymbolAddress((void**)&h,   g_h);
    cudaGetSymbolAddress((void**)&hn,  g_hn);
    cudaGetSymbolAddress((void**)&kqb, g_kq);
    cudaGetSymbolAddress((void**)&vb,  g_v);
    cudaGetSymbolAddress((void**)&ob,  g_o);
    cudaGetSymbolAddress((void**)&xo,  g_xo);
    cudaGetSymbolAddress((void**)&mlp, g_mlp);

    float* out0     = (float*)d_out;                       // [4096, 512]
    float* attn_out = out0 + (size_t)NTOK * INPUT_DIM;     // [4096, 1024]

    cudaFuncSetAttribute(attn_kernel, cudaFuncAttributeMaxDynamicSharedMemorySize, ATT_SMEM);

    // 1. h = x @ wte_w + wte_b + wpe
    sgemm_kernel<EPI_EMBED><<<dim3(DMODEL / BN, NTOK / BM), 256>>>(
        NTOK, DMODEL, INPUT_DIM, x, wte_w, wte_b, wpe, h);
    // 2. hn = LN1(h)
    ln_kernel<<<NTOK, 256>>>(h, ln1_w, ln1_b, hn);
    // 3. kq = hn @ kq_w + kq_b
    sgemm_kernel<EPI_BIAS><<<dim3(2 * DMODEL / BN, NTOK / BM), 256>>>(
        NTOK, 2 * DMODEL, DMODEL, hn, kq_w, kq_b, nullptr, kqb);
    // 4. v = hn @ v_w + v_b
    sgemm_kernel<EPI_BIAS><<<dim3(DMODEL / BN, NTOK / BM), 256>>>(
        NTOK, DMODEL, DMODEL, hn, v_w, v_b, nullptr, vb);
    // 5. attention
    attn_kernel<<<dim3(LSEQ / 64, BATCH * NHEAD), 256, ATT_SMEM>>>(kqb, vb, ob);
    // 6. attn_out = hn + (o @ ao_w + ao_b)
    sgemm_kernel<EPI_RES><<<dim3(DMODEL / BN, NTOK / BM), 256>>>(
        NTOK, DMODEL, DMODEL, ob, ao_w, ao_b, hn, attn_out);
    // 7. xo = LN2(attn_out)
    ln_kernel<<<NTOK, 256>>>(attn_out, ln2_w, ln2_b, xo);
    // 8. mlp = gelu(xo @ fc_w + fc_b)
    sgemm_kernel<EPI_GELU><<<dim3(MLPH / BN, NTOK / BM), 256>>>(
        NTOK, MLPH, DMODEL, xo, fc_w, fc_b, nullptr, mlp);
    // 9. out = mlp @ proj_w + proj_b
    sgemm_kernel<EPI_BIAS><<<dim3(INPUT_DIM / BN, NTOK / BM), 256>>>(
        NTOK, INPUT_DIM, MLPH, mlp, proj_w, proj_b, nullptr, out0);
}

// round 4
// speedup vs baseline: 2.0098x; 1.9991x over previous
#include <cuda_runtime.h>
#include <cuda_bf16.h>
#include <math.h>
#include <stdint.h>

#define BATCH 2
#define LSEQ 2048
#define NTOK (BATCH*LSEQ)
#define INPUT_DIM 512
#define DMODEL 1024
#define NHEAD 16
#define HD 64
#define MLPH 4096
#define LN_EPS 1e-5f

// fp32 scratch
__device__ float g_h [NTOK*DMODEL];
__device__ float g_hn[NTOK*DMODEL];
__device__ float g_kq[NTOK*2*DMODEL];
__device__ float g_v [NTOK*DMODEL];
// bf16 split activations
__device__ __nv_bfloat16 g_x_hi[NTOK*INPUT_DIM], g_x_lo[NTOK*INPUT_DIM];
__device__ __nv_bfloat16 g_hn_hi[NTOK*DMODEL],   g_hn_lo[NTOK*DMODEL];
__device__ __nv_bfloat16 g_o_hi[NTOK*DMODEL],    g_o_lo[NTOK*DMODEL];
__device__ __nv_bfloat16 g_xo_hi[NTOK*DMODEL],   g_xo_lo[NTOK*DMODEL];
__device__ __nv_bfloat16 g_ml_hi[NTOK*MLPH],     g_ml_lo[NTOK*MLPH];
// bf16 split transposed weights [N][K]
__device__ __nv_bfloat16 g_wte_hi[DMODEL*INPUT_DIM], g_wte_lo[DMODEL*INPUT_DIM];
__device__ __nv_bfloat16 g_kqw_hi[2*DMODEL*DMODEL],  g_kqw_lo[2*DMODEL*DMODEL];
__device__ __nv_bfloat16 g_vw_hi[DMODEL*DMODEL],     g_vw_lo[DMODEL*DMODEL];
__device__ __nv_bfloat16 g_aow_hi[DMODEL*DMODEL],    g_aow_lo[DMODEL*DMODEL];
__device__ __nv_bfloat16 g_fcw_hi[MLPH*DMODEL],      g_fcw_lo[MLPH*DMODEL];
__device__ __nv_bfloat16 g_pjw_hi[INPUT_DIM*MLPH],   g_pjw_lo[INPUT_DIM*MLPH];

__device__ __forceinline__ void split2(float v, __nv_bfloat16& hi, __nv_bfloat16& lo) {
    hi = __float2bfloat16(v);
    lo = __float2bfloat16(v - __bfloat162float(hi));
}
__device__ __forceinline__ uint32_t pack2(__nv_bfloat16 a, __nv_bfloat16 b) {
    __nv_bfloat162 t = __halves2bfloat162(a, b);
    return *reinterpret_cast<uint32_t*>(&t);
}
__device__ __forceinline__ uint32_t smem_u32(const void* p) {
    return (uint32_t)__cvta_generic_to_shared(p);
}
__device__ __forceinline__ void cpasync16(uint32_t dst, const void* src) {
    asm volatile("cp.async.cg.shared.global [%0], [%1], 16;" :: "r"(dst), "l"(src));
}
__device__ __forceinline__ void ldm_x4(uint32_t* r, uint32_t a) {
    asm volatile("ldmatrix.sync.aligned.m8n8.x4.shared.b16 {%0,%1,%2,%3}, [%4];"
                 : "=r"(r[0]), "=r"(r[1]), "=r"(r[2]), "=r"(r[3]) : "r"(a));
}
__device__ __forceinline__ void ldm_x2(uint32_t* r, uint32_t a) {
    asm volatile("ldmatrix.sync.aligned.m8n8.x2.shared.b16 {%0,%1}, [%2];"
                 : "=r"(r[0]), "=r"(r[1]) : "r"(a));
}
__device__ __forceinline__ void mma_bf16(float* d, const uint32_t* a, const uint32_t* b) {
    asm volatile("mma.sync.aligned.m16n8k16.row.col.f32.bf16.bf16.f32 "
                 "{%0,%1,%2,%3}, {%4,%5,%6,%7}, {%8,%9}, {%0,%1,%2,%3};"
                 : "+f"(d[0]), "+f"(d[1]), "+f"(d[2]), "+f"(d[3])
                 : "r"(a[0]), "r"(a[1]), "r"(a[2]), "r"(a[3]), "r"(b[0]), "r"(b[1]));
}

// ---- weight transpose + split: W[K][N] fp32 -> Wt[N][K] bf16 hi/lo ----
__global__ __launch_bounds__(256)
void wsplit_kernel(const float* __restrict__ W, int K, int N,
                   __nv_bfloat16* __restrict__ hi, __nv_bfloat16* __restrict__ lo)
{
    __shared__ float tile[32][33];
    const int k0 = blockIdx.y * 32, n0 = blockIdx.x * 32;
    const int tx = threadIdx.x, ty = threadIdx.y;
#pragma unroll
    for (int i = 0; i < 32; i += 8)
        tile[ty + i][tx] = W[(size_t)(k0 + ty + i) * N + n0 + tx];
    __syncthreads();
#pragma unroll
    for (int i = 0; i < 32; i += 8) {
        __nv_bfloat16 h_, l_;
        split2(tile[tx][ty + i], h_, l_);
        size_t o = (size_t)(n0 + ty + i) * K + k0 + tx;
        hi[o] = h_; lo[o] = l_;
    }
}

__global__ __launch_bounds__(256)
void xsplit_kernel(const float* __restrict__ x, __nv_bfloat16* __restrict__ hi,
                   __nv_bfloat16* __restrict__ lo, int n)
{
    int i = blockIdx.x * 256 + threadIdx.x;
    if (i < n) { __nv_bfloat16 h_, l_; split2(x[i], h_, l_); hi[i] = h_; lo[i] = l_; }
}

// ---- HMMA GEMM: C[M,N] = A[M,K] @ W[K,N], split-3 bf16, tile 128x128x32 ----
enum { EP_EMBED = 0, EP_BIAS = 1, EP_RES = 2, EP_GELU = 3 };
#define HM_SMEM (2*32768)

template <int EPI>
__global__ __launch_bounds__(256)
void hmma_gemm(int M, int N, int K,
               const __nv_bfloat16* __restrict__ Ahi, const __nv_bfloat16* __restrict__ Alo,
               const __nv_bfloat16* __restrict__ Bhi, const __nv_bfloat16* __restrict__ Blo,
               const float* __restrict__ bias, const float* __restrict__ extra,
               float* __restrict__ Cf,
               __nv_bfloat16* __restrict__ Chi, __nv_bfloat16* __restrict__ Clo)
{
    extern __shared__ char dsm[];
    const uint32_t sbase = smem_u32(dsm);
    const int tid = threadIdx.x, wid = tid >> 5, lane = tid & 31;
    const int m0 = blockIdx.y * 128, n0 = blockIdx.x * 128;
    const int wm = (wid & 1) * 64, wn = (wid >> 1) * 32;

    float acc[4][4][4];
#pragma unroll
    for (int i = 0; i < 4; i++)
#pragma unroll
        for (int j = 0; j < 4; j++)
#pragma unroll
            for (int q = 0; q < 4; q++) acc[i][j][q] = 0.f;

    // lane-constant ldmatrix offsets (64B row stride, 16B-chunk XOR swizzle)
    uint32_t a_off[4], a_sw[4];
    const uint32_t a_half = lane >> 4;            // chunk half from block id
#pragma unroll
    for (int i = 0; i < 4; i++) {
        int row = wm + i * 16 + (lane & 7) + ((lane >> 3) & 1) * 8;
        a_off[i] = row * 64;
        a_sw[i]  = (row >> 1) & 3;
    }
    uint32_t b_off[4], b_sw[4];
    const uint32_t b_half = (lane >> 3) & 1;
#pragma unroll
    for (int j = 0; j < 4; j++) {
        int row = wn + j * 8 + (lane & 7);
        b_off[j] = row * 64;
        b_sw[j]  = (row >> 1) & 3;
    }

    const int nch = K >> 5;

    // stage chunk i into buffer (i&1)
    auto stage = [&](int i) {
        const uint32_t buf = sbase + (i & 1) * 32768;
        const int kofs = i << 5;
#pragma unroll
        for (int t = 0; t < 4; t++) {
            const __nv_bfloat16* src = (t == 0) ? Ahi : (t == 1) ? Alo : (t == 2) ? Bhi : Blo;
            const int rb = (t < 2) ? m0 : n0;
            const uint32_t db = buf + t * 8192;
#pragma unroll
            for (int u = 0; u < 2; u++) {
                int idx = tid + u * 256;
                int row = idx >> 2, c = idx & 3;
                cpasync16(db + row * 64 + ((c ^ ((row >> 1) & 3)) << 4),
                          src + (size_t)(rb + row) * K + kofs + c * 8);
            }
        }
    };

    stage(0);
    asm volatile("cp.async.commit_group;" ::: "memory");

    for (int i = 0; i < nch; i++) {
        if (i + 1 < nch) {
            stage(i + 1);
            asm volatile("cp.async.commit_group;" ::: "memory");
            asm volatile("cp.async.wait_group 1;" ::: "memory");
        } else {
            asm volatile("cp.async.wait_group 0;" ::: "memory");
        }
        __syncthreads();

        const uint32_t buf = sbase + (i & 1) * 32768;
#pragma unroll
        for (int p = 0; p < 3; p++) {
            const uint32_t ab = buf + (p == 1 ? 8192 : 0);
            const uint32_t bb = buf + (p == 2 ? 24576 : 16384);
#pragma unroll
            for (int kk = 0; kk < 2; kk++) {
                uint32_t af[4][4], bf[4][2];
#pragma unroll
                for (int t = 0; t < 4; t++)
                    ldm_x4(af[t], ab + a_off[t] + (((kk * 2 + a_half) ^ a_sw[t]) << 4));
#pragma unroll
                for (int t = 0; t < 4; t++)
                    ldm_x2(bf[t], bb + b_off[t] + (((kk * 2 + b_half) ^ b_sw[t]) << 4));
#pragma unroll
                for (int ti = 0; ti < 4; ti++)
#pragma unroll
                    for (int tj = 0; tj < 4; tj++)
                        mma_bf16(acc[ti][tj], af[ti], bf[tj]);
            }
        }
        __syncthreads();
    }

    // epilogue from registers
#pragma unroll
    for (int i = 0; i < 4; i++) {
#pragma unroll
        for (int half = 0; half < 2; half++) {
            const int row = m0 + wm + i * 16 + (lane >> 2) + half * 8;
#pragma unroll
            for (int j = 0; j < 4; j++) {
                const int col = n0 + wn + j * 8 + (lane & 3) * 2;
                float2 bv = *reinterpret_cast<const float2*>(bias + col);
                float v0 = acc[i][j][half * 2 + 0] + bv.x;
                float v1 = acc[i][j][half * 2 + 1] + bv.y;
                if (EPI == EP_EMBED || EPI == EP_RES) {
                    const int er = (EPI == EP_EMBED) ? (row & (LSEQ - 1)) : row;
                    float2 ev = *reinterpret_cast<const float2*>(extra + (size_t)er * N + col);
                    v0 += ev.x; v1 += ev.y;
                }
                if (EPI == EP_GELU) {
                    v0 = 0.5f * v0 * (1.f + erff(v0 * 0.70710678118654752f));
                    v1 = 0.5f * v1 * (1.f + erff(v1 * 0.70710678118654752f));
                    __nv_bfloat16 h0, l0, h1, l1;
                    split2(v0, h0, l0); split2(v1, h1, l1);
                    *reinterpret_cast<uint32_t*>(Chi + (size_t)row * N + col) = pack2(h0, h1);
                    *reinterpret_cast<uint32_t*>(Clo + (size_t)row * N + col) = pack2(l0, l1);
                } else {
                    *reinterpret_cast<float2*>(Cf + (size_t)row * N + col) = make_float2(v0, v1);
                }
            }
        }
    }
}

// ---- LayerNorm (fp32 out and/or bf16 split out) ----
template <bool WF32, bool WSPLIT>
__global__ __launch_bounds__(256)
void ln_kernel(const float* __restrict__ x, const float* __restrict__ w,
               const float* __restrict__ b, float* __restrict__ y,
               __nv_bfloat16* __restrict__ yhi, __nv_bfloat16* __restrict__ ylo)
{
    const int row = blockIdx.x, c = threadIdx.x * 4;
    float4 v = *reinterpret_cast<const float4*>(x + (size_t)row * DMODEL + c);
    float s = v.x + v.y + v.z + v.w;
    float sq = v.x*v.x + v.y*v.y + v.z*v.z + v.w*v.w;
#pragma unroll
    for (int o = 16; o; o >>= 1) {
        s += __shfl_xor_sync(~0u, s, o); sq += __shfl_xor_sync(~0u, sq, o);
    }
    __shared__ float ss[8], ssq[8];
    const int warp = threadIdx.x >> 5, lane = threadIdx.x & 31;
    if (lane == 0) { ss[warp] = s; ssq[warp] = sq; }
    __syncthreads();
    float tot = 0.f, totq = 0.f;
#pragma unroll
    for (int i = 0; i < 8; i++) { tot += ss[i]; totq += ssq[i]; }
    const float mu = tot / DMODEL, var = totq / DMODEL - mu * mu;
    const float inv = rsqrtf(var + LN_EPS);
    float4 wv = *reinterpret_cast<const float4*>(w + c);
    float4 bv = *reinterpret_cast<const float4*>(b + c);
    float4 o;
    o.x = (v.x-mu)*inv*wv.x + bv.x; o.y = (v.y-mu)*inv*wv.y + bv.y;
    o.z = (v.z-mu)*inv*wv.z + bv.z; o.w = (v.w-mu)*inv*wv.w + bv.w;
    if (WF32) *reinterpret_cast<float4*>(y + (size_t)row * DMODEL + c) = o;
    if (WSPLIT) {
        __nv_bfloat16 h0,l0,h1,l1,h2,l2,h3,l3;
        split2(o.x,h0,l0); split2(o.y,h1,l1); split2(o.z,h2,l2); split2(o.w,h3,l3);
        *reinterpret_cast<uint2*>(yhi + (size_t)row*DMODEL + c) = make_uint2(pack2(h0,h1), pack2(h2,h3));
        *reinterpret_cast<uint2*>(ylo + (size_t)row*DMODEL + c) = make_uint2(pack2(l0,l1), pack2(l2,l3));
    }
}

// ---- Flash attention (causal fp32), split bf16 output ----
#define ATT_PAD 68
#define ATT_SMEM (4*64*ATT_PAD*4)
__global__ __launch_bounds__(256)
void attn_kernel(const float* __restrict__ kq, const float* __restrict__ vbuf,
                 __nv_bfloat16* __restrict__ ohi, __nv_bfloat16* __restrict__ olo)
{
    extern __shared__ float sm[];
    float* Qt = sm;
    float* Kt = sm + 64*ATT_PAD;
    float* Vs = sm + 2*64*ATT_PAD;
    float* Ps = sm + 3*64*ATT_PAD;
    const int tid = threadIdx.x, qtile = blockIdx.x, bh = blockIdx.y;
    const int bidx = bh >> 4, h = bh & 15;
    const int rowbase = bidx * LSEQ, q0 = qtile * 64;
    const int tr = tid >> 4, tc = tid & 15;

#pragma unroll
    for (int it = 0; it < 4; it++) {
        int idx = tid + it*256, r = idx >> 4, d4 = (idx & 15) << 2;
        float4 qv = *reinterpret_cast<const float4*>(
            kq + (size_t)(rowbase + q0 + r)*(2*DMODEL) + DMODEL + h*HD + d4);
        Qt[(d4+0)*ATT_PAD+r] = qv.x*0.125f; Qt[(d4+1)*ATT_PAD+r] = qv.y*0.125f;
        Qt[(d4+2)*ATT_PAD+r] = qv.z*0.125f; Qt[(d4+3)*ATT_PAD+r] = qv.w*0.125f;
    }
    float m[4], l[4], o[4][4];
#pragma unroll
    for (int a = 0; a < 4; a++) {
        m[a] = -INFINITY; l[a] = 0.f;
#pragma unroll
        for (int c = 0; c < 4; c++) o[a][c] = 0.f;
    }
    for (int jt = 0; jt <= qtile; jt++) {
        __syncthreads();
        const int n0 = jt * 64;
#pragma unroll
        for (int it = 0; it < 4; it++) {
            int idx = tid + it*256, r = idx >> 4, d4 = (idx & 15) << 2;
            float4 kv = *reinterpret_cast<const float4*>(
                kq + (size_t)(rowbase + n0 + r)*(2*DMODEL) + h*HD + d4);
            Kt[(d4+0)*ATT_PAD+r] = kv.x; Kt[(d4+1)*ATT_PAD+r] = kv.y;
            Kt[(d4+2)*ATT_PAD+r] = kv.z; Kt[(d4+3)*ATT_PAD+r] = kv.w;
            *reinterpret_cast<float4*>(&Vs[r*ATT_PAD + d4]) =
                *reinterpret_cast<const float4*>(vbuf + (size_t)(rowbase + n0 + r)*DMODEL + h*HD + d4);
        }
        __syncthreads();
        float s[4][4];
#pragma unroll
        for (int a = 0; a < 4; a++)
#pragma unroll
            for (int c = 0; c < 4; c++) s[a][c] = 0.f;
#pragma unroll 4
        for (int d = 0; d < 64; d++) {
            float4 qa = *reinterpret_cast<const float4*>(&Qt[d*ATT_PAD + 4*tr]);
            float4 kb = *reinterpret_cast<const float4*>(&Kt[d*ATT_PAD + 4*tc]);
            float ra[4] = {qa.x, qa.y, qa.z, qa.w}, rb[4] = {kb.x, kb.y, kb.z, kb.w};
#pragma unroll
            for (int a = 0; a < 4; a++)
#pragma unroll
                for (int c = 0; c < 4; c++) s[a][c] = fmaf(ra[a], rb[c], s[a][c]);
        }
        if (jt == qtile) {
#pragma unroll
            for (int a = 0; a < 4; a++)
#pragma unroll
                for (int c = 0; c < 4; c++)
                    if (4*tc + c > 4*tr + a) s[a][c] = -INFINITY;
        }
#pragma unroll
        for (int a = 0; a < 4; a++) {
            float mx = fmaxf(fmaxf(s[a][0], s[a][1]), fmaxf(s[a][2], s[a][3]));
#pragma unroll
            for (int off = 1; off < 16; off <<= 1) mx = fmaxf(mx, __shfl_xor_sync(~0u, mx, off));
            const float nm = fmaxf(m[a], mx), corr = expf(m[a] - nm);
            float rs = 0.f;
#pragma unroll
            for (int c = 0; c < 4; c++) { s[a][c] = expf(s[a][c] - nm); rs += s[a][c]; }
#pragma unroll
            for (int off = 1; off < 16; off <<= 1) rs += __shfl_xor_sync(~0u, rs, off);
            l[a] = l[a]*corr + rs; m[a] = nm;
#pragma unroll
            for (int c = 0; c < 4; c++) o[a][c] *= corr;
            *reinterpret_cast<float4*>(&Ps[(4*tr+a)*ATT_PAD + 4*tc]) =
                make_float4(s[a][0], s[a][1], s[a][2], s[a][3]);
        }
        __syncthreads();
#pragma unroll 4
        for (int j = 0; j < 64; j++) {
            float4 vb = *reinterpret_cast<const float4*>(&Vs[j*ATT_PAD + 4*tc]);
            float rb[4] = {vb.x, vb.y, vb.z, vb.w};
#pragma unroll
            for (int a = 0; a < 4; a++) {
                float p = Ps[(4*tr+a)*ATT_PAD + j];
#pragma unroll
                for (int c = 0; c < 4; c++) o[a][c] = fmaf(p, rb[c], o[a][c]);
            }
        }
    }
#pragma unroll
    for (int a = 0; a < 4; a++) {
        const float inv = 1.f / l[a];
        size_t oi = (size_t)(rowbase + q0 + 4*tr + a)*DMODEL + h*HD + 4*tc;
        __nv_bfloat16 h0,l0,h1,l1,h2,l2,h3,l3;
        split2(o[a][0]*inv,h0,l0); split2(o[a][1]*inv,h1,l1);
        split2(o[a][2]*inv,h2,l2); split2(o[a][3]*inv,h3,l3);
        *reinterpret_cast<uint2*>(ohi + oi) = make_uint2(pack2(h0,h1), pack2(h2,h3));
        *reinterpret_cast<uint2*>(olo + oi) = make_uint2(pack2(l0,l1), pack2(l2,l3));
    }
}

extern "C" void kernel_launch(void* const* d_in, const int* in_sizes, int n_in,
                              void* d_out, int out_size)
{
    const float* x      = (const float*)d_in[0];
    const float* wte_w  = (const float*)d_in[1];
    const float* wte_b  = (const float*)d_in[2];
    const float* wpe    = (const float*)d_in[3];
    const float* ln1_w  = (const float*)d_in[4];
    const float* ln1_b  = (const float*)d_in[5];
    const float* kq_w   = (const float*)d_in[6];
    const float* kq_b   = (const float*)d_in[7];
    const float* v_w    = (const float*)d_in[8];
    const float* v_b    = (const float*)d_in[9];
    const float* ao_w   = (const float*)d_in[10];
    const float* ao_b   = (const float*)d_in[11];
    const float* ln2_w  = (const float*)d_in[12];
    const float* ln2_b  = (const float*)d_in[13];
    const float* fc_w   = (const float*)d_in[14];
    const float* fc_b   = (const float*)d_in[15];
    const float* proj_w = (const float*)d_in[16];
    const float* proj_b = (const float*)d_in[17];

    float *h, *hn, *kqb, *vb;
    cudaGetSymbolAddress((void**)&h, g_h);
    cudaGetSymbolAddress((void**)&hn, g_hn);
    cudaGetSymbolAddress((void**)&kqb, g_kq);
    cudaGetSymbolAddress((void**)&vb, g_v);
    __nv_bfloat16 *xhi,*xlo,*hnhi,*hnlo,*ohi,*olo,*xohi,*xolo,*mlhi,*mllo;
    __nv_bfloat16 *wtehi,*wtelo,*kqwhi,*kqwlo,*vwhi,*vwlo,*aowhi,*aowlo,*fcwhi,*fcwlo,*pjwhi,*pjwlo;
    cudaGetSymbolAddress((void**)&xhi, g_x_hi);   cudaGetSymbolAddress((void**)&xlo, g_x_lo);
    cudaGetSymbolAddress((void**)&hnhi, g_hn_hi); cudaGetSymbolAddress((void**)&hnlo, g_hn_lo);
    cudaGetSymbolAddress((void**)&ohi, g_o_hi);   cudaGetSymbolAddress((void**)&olo, g_o_lo);
    cudaGetSymbolAddress((void**)&xohi, g_xo_hi); cudaGetSymbolAddress((void**)&xolo, g_xo_lo);
    cudaGetSymbolAddress((void**)&mlhi, g_ml_hi); cudaGetSymbolAddress((void**)&mllo, g_ml_lo);
    cudaGetSymbolAddress((void**)&wtehi, g_wte_hi); cudaGetSymbolAddress((void**)&wtelo, g_wte_lo);
    cudaGetSymbolAddress((void**)&kqwhi, g_kqw_hi); cudaGetSymbolAddress((void**)&kqwlo, g_kqw_lo);
    cudaGetSymbolAddress((void**)&vwhi, g_vw_hi);   cudaGetSymbolAddress((void**)&vwlo, g_vw_lo);
    cudaGetSymbolAddress((void**)&aowhi, g_aow_hi); cudaGetSymbolAddress((void**)&aowlo, g_aow_lo);
    cudaGetSymbolAddress((void**)&fcwhi, g_fcw_hi); cudaGetSymbolAddress((void**)&fcwlo, g_fcw_lo);
    cudaGetSymbolAddress((void**)&pjwhi, g_pjw_hi); cudaGetSymbolAddress((void**)&pjwlo, g_pjw_lo);

    float* out0     = (float*)d_out;
    float* attn_out = out0 + (size_t)NTOK * INPUT_DIM;

    cudaFuncSetAttribute(hmma_gemm<EP_EMBED>, cudaFuncAttributeMaxDynamicSharedMemorySize, HM_SMEM);
    cudaFuncSetAttribute(hmma_gemm<EP_BIAS>,  cudaFuncAttributeMaxDynamicSharedMemorySize, HM_SMEM);
    cudaFuncSetAttribute(hmma_gemm<EP_RES>,   cudaFuncAttributeMaxDynamicSharedMemorySize, HM_SMEM);
    cudaFuncSetAttribute(hmma_gemm<EP_GELU>,  cudaFuncAttributeMaxDynamicSharedMemorySize, HM_SMEM);
    cudaFuncSetAttribute(attn_kernel, cudaFuncAttributeMaxDynamicSharedMemorySize, ATT_SMEM);

    dim3 wsb(32, 8);
    xsplit_kernel<<<(NTOK*INPUT_DIM)/256, 256>>>(x, xhi, xlo, NTOK*INPUT_DIM);
    wsplit_kernel<<<dim3(DMODEL/32, INPUT_DIM/32), wsb>>>(wte_w, INPUT_DIM, DMODEL, wtehi, wtelo);
    wsplit_kernel<<<dim3(2*DMODEL/32, DMODEL/32), wsb>>>(kq_w, DMODEL, 2*DMODEL, kqwhi, kqwlo);
    wsplit_kernel<<<dim3(DMODEL/32, DMODEL/32), wsb>>>(v_w, DMODEL, DMODEL, vwhi, vwlo);
    wsplit_kernel<<<dim3(DMODEL/32, DMODEL/32), wsb>>>(ao_w, DMODEL, DMODEL, aowhi, aowlo);
    wsplit_kernel<<<dim3(MLPH/32, DMODEL/32), wsb>>>(fc_w, DMODEL, MLPH, fcwhi, fcwlo);
    wsplit_kernel<<<dim3(INPUT_DIM/32, MLPH/32), wsb>>>(proj_w, MLPH, INPUT_DIM, pjwhi, pjwlo);

    hmma_gemm<EP_EMBED><<<dim3(DMODEL/128, NTOK/128), 256, HM_SMEM>>>(
        NTOK, DMODEL, INPUT_DIM, xhi, xlo, wtehi, wtelo, wte_b, wpe, h, nullptr, nullptr);
    ln_kernel<true, true><<<NTOK, 256>>>(h, ln1_w, ln1_b, hn, hnhi, hnlo);
    hmma_gemm<EP_BIAS><<<dim3(2*DMODEL/128, NTOK/128), 256, HM_SMEM>>>(
        NTOK, 2*DMODEL, DMODEL, hnhi, hnlo, kqwhi, kqwlo, kq_b, nullptr, kqb, nullptr, nullptr);
    hmma_gemm<EP_BIAS><<<dim3(DMODEL/128, NTOK/128), 256, HM_SMEM>>>(
        NTOK, DMODEL, DMODEL, hnhi, hnlo, vwhi, vwlo, v_b, nullptr, vb, nullptr, nullptr);
    attn_kernel<<<dim3(LSEQ/64, BATCH*NHEAD), 256, ATT_SMEM>>>(kqb, vb, ohi, olo);
    hmma_gemm<EP_RES><<<dim3(DMODEL/128, NTOK/128), 256, HM_SMEM>>>(
        NTOK, DMODEL, DMODEL, ohi, olo, aowhi, aowlo, ao_b, hn, attn_out, nullptr, nullptr);
    ln_kernel<false, true><<<NTOK, 256>>>(attn_out, ln2_w, ln2_b, nullptr, xohi, xolo);
    hmma_gemm<EP_GELU><<<dim3(MLPH/128, NTOK/128), 256, HM_SMEM>>>(
        NTOK, MLPH, DMODEL, xohi, xolo, fcwhi, fcwlo, fc_b, nullptr, nullptr, mlhi, mllo);
    hmma_gemm<EP_BIAS><<<dim3(INPUT_DIM/128, NTOK/128), 256, HM_SMEM>>>(
        NTOK, INPUT_DIM, MLPH, mlhi, mllo, pjwhi, pjwlo, proj_b, nullptr, out0, nullptr, nullptr);
}

// round 5
// speedup vs baseline: 2.9440x; 1.4648x over previous
#include <cuda_runtime.h>
#include <cuda_bf16.h>
#include <math.h>
#include <stdint.h>

#define BATCH 2
#define LSEQ 2048
#define NTOK (BATCH*LSEQ)
#define INPUT_DIM 512
#define DMODEL 1024
#define NHEAD 16
#define HD 64
#define MLPH 4096
#define LN_EPS 1e-5f

// fp32 scratch
__device__ float g_h [NTOK*DMODEL];
__device__ float g_hn[NTOK*DMODEL];
// bf16 split activations
__device__ __nv_bfloat16 g_x_hi[NTOK*INPUT_DIM], g_x_lo[NTOK*INPUT_DIM];
__device__ __nv_bfloat16 g_hn_hi[NTOK*DMODEL],   g_hn_lo[NTOK*DMODEL];
__device__ __nv_bfloat16 g_kq_hi[NTOK*2*DMODEL], g_kq_lo[NTOK*2*DMODEL];
__device__ __nv_bfloat16 g_v_hi[NTOK*DMODEL],    g_v_lo[NTOK*DMODEL];
__device__ __nv_bfloat16 g_o_hi[NTOK*DMODEL],    g_o_lo[NTOK*DMODEL];
__device__ __nv_bfloat16 g_xo_hi[NTOK*DMODEL],   g_xo_lo[NTOK*DMODEL];
__device__ __nv_bfloat16 g_ml_hi[NTOK*MLPH],     g_ml_lo[NTOK*MLPH];
// bf16 split transposed weights [N][K]
__device__ __nv_bfloat16 g_wte_hi[DMODEL*INPUT_DIM], g_wte_lo[DMODEL*INPUT_DIM];
__device__ __nv_bfloat16 g_kqw_hi[2*DMODEL*DMODEL],  g_kqw_lo[2*DMODEL*DMODEL];
__device__ __nv_bfloat16 g_vw_hi[DMODEL*DMODEL],     g_vw_lo[DMODEL*DMODEL];
__device__ __nv_bfloat16 g_aow_hi[DMODEL*DMODEL],    g_aow_lo[DMODEL*DMODEL];
__device__ __nv_bfloat16 g_fcw_hi[MLPH*DMODEL],      g_fcw_lo[MLPH*DMODEL];
__device__ __nv_bfloat16 g_pjw_hi[INPUT_DIM*MLPH],   g_pjw_lo[INPUT_DIM*MLPH];

__device__ __forceinline__ void split2(float v, __nv_bfloat16& hi, __nv_bfloat16& lo) {
    hi = __float2bfloat16(v);
    lo = __float2bfloat16(v - __bfloat162float(hi));
}
__device__ __forceinline__ uint32_t pack2(__nv_bfloat16 a, __nv_bfloat16 b) {
    __nv_bfloat162 t = __halves2bfloat162(a, b);
    return *reinterpret_cast<uint32_t*>(&t);
}
__device__ __forceinline__ uint32_t pack2f(float a, float b) {  // hi parts
    return pack2(__float2bfloat16(a), __float2bfloat16(b));
}
__device__ __forceinline__ uint32_t smem_u32(const void* p) {
    return (uint32_t)__cvta_generic_to_shared(p);
}
__device__ __forceinline__ void cpasync16(uint32_t dst, const void* src) {
    asm volatile("cp.async.cg.shared.global [%0], [%1], 16;" :: "r"(dst), "l"(src));
}
__device__ __forceinline__ void ldm_x4(uint32_t* r, uint32_t a) {
    asm volatile("ldmatrix.sync.aligned.m8n8.x4.shared.b16 {%0,%1,%2,%3}, [%4];"
                 : "=r"(r[0]), "=r"(r[1]), "=r"(r[2]), "=r"(r[3]) : "r"(a));
}
__device__ __forceinline__ void ldm_x2(uint32_t* r, uint32_t a) {
    asm volatile("ldmatrix.sync.aligned.m8n8.x2.shared.b16 {%0,%1}, [%2];"
                 : "=r"(r[0]), "=r"(r[1]) : "r"(a));
}
__device__ __forceinline__ void ldm_x2t(uint32_t* r, uint32_t a) {
    asm volatile("ldmatrix.sync.aligned.m8n8.x2.trans.shared.b16 {%0,%1}, [%2];"
                 : "=r"(r[0]), "=r"(r[1]) : "r"(a));
}
__device__ __forceinline__ void mma_bf16(float* d, const uint32_t* a, const uint32_t* b) {
    asm volatile("mma.sync.aligned.m16n8k16.row.col.f32.bf16.bf16.f32 "
                 "{%0,%1,%2,%3}, {%4,%5,%6,%7}, {%8,%9}, {%0,%1,%2,%3};"
                 : "+f"(d[0]), "+f"(d[1]), "+f"(d[2]), "+f"(d[3])
                 : "r"(a[0]), "r"(a[1]), "r"(a[2]), "r"(a[3]), "r"(b[0]), "r"(b[1]));
}

// ---- weight transpose + split ----
__global__ __launch_bounds__(256)
void wsplit_kernel(const float* __restrict__ W, int K, int N,
                   __nv_bfloat16* __restrict__ hi, __nv_bfloat16* __restrict__ lo)
{
    __shared__ float tile[32][33];
    const int k0 = blockIdx.y * 32, n0 = blockIdx.x * 32;
    const int tx = threadIdx.x, ty = threadIdx.y;
#pragma unroll
    for (int i = 0; i < 32; i += 8)
        tile[ty + i][tx] = W[(size_t)(k0 + ty + i) * N + n0 + tx];
    __syncthreads();
#pragma unroll
    for (int i = 0; i < 32; i += 8) {
        __nv_bfloat16 h_, l_;
        split2(tile[tx][ty + i], h_, l_);
        size_t o = (size_t)(n0 + ty + i) * K + k0 + tx;
        hi[o] = h_; lo[o] = l_;
    }
}

__global__ __launch_bounds__(256)
void xsplit_kernel(const float* __restrict__ x, __nv_bfloat16* __restrict__ hi,
                   __nv_bfloat16* __restrict__ lo, int n)
{
    int i = blockIdx.x * 256 + threadIdx.x;
    if (i < n) { __nv_bfloat16 h_, l_; split2(x[i], h_, l_); hi[i] = h_; lo[i] = l_; }
}

// ---- HMMA GEMM: split-3 bf16, tile 128x128x32 ----
enum { EP_EMBED = 0, EP_BIAS = 1, EP_RES = 2, EP_GELU = 3, EP_SPLIT = 4 };
#define HM_SMEM (2*32768)

template <int EPI>
__global__ __launch_bounds__(256)
void hmma_gemm(int M, int N, int K,
               const __nv_bfloat16* __restrict__ Ahi, const __nv_bfloat16* __restrict__ Alo,
               const __nv_bfloat16* __restrict__ Bhi, const __nv_bfloat16* __restrict__ Blo,
               const float* __restrict__ bias, const float* __restrict__ extra,
               float* __restrict__ Cf,
               __nv_bfloat16* __restrict__ Chi, __nv_bfloat16* __restrict__ Clo)
{
    extern __shared__ char dsm[];
    const uint32_t sbase = smem_u32(dsm);
    const int tid = threadIdx.x, wid = tid >> 5, lane = tid & 31;
    const int m0 = blockIdx.y * 128, n0 = blockIdx.x * 128;
    const int wm = (wid & 1) * 64, wn = (wid >> 1) * 32;

    float acc[4][4][4];
#pragma unroll
    for (int i = 0; i < 4; i++)
#pragma unroll
        for (int j = 0; j < 4; j++)
#pragma unroll
            for (int q = 0; q < 4; q++) acc[i][j][q] = 0.f;

    uint32_t a_off[4], a_sw[4];
    const uint32_t a_half = lane >> 4;
#pragma unroll
    for (int i = 0; i < 4; i++) {
        int row = wm + i * 16 + (lane & 7) + ((lane >> 3) & 1) * 8;
        a_off[i] = row * 64;
        a_sw[i]  = (row >> 1) & 3;
    }
    uint32_t b_off[4], b_sw[4];
    const uint32_t b_half = (lane >> 3) & 1;
#pragma unroll
    for (int j = 0; j < 4; j++) {
        int row = wn + j * 8 + (lane & 7);
        b_off[j] = row * 64;
        b_sw[j]  = (row >> 1) & 3;
    }

    const int nch = K >> 5;
    auto stage = [&](int i) {
        const uint32_t buf = sbase + (i & 1) * 32768;
        const int kofs = i << 5;
#pragma unroll
        for (int t = 0; t < 4; t++) {
            const __nv_bfloat16* src = (t == 0) ? Ahi : (t == 1) ? Alo : (t == 2) ? Bhi : Blo;
            const int rb = (t < 2) ? m0 : n0;
            const uint32_t db = buf + t * 8192;
#pragma unroll
            for (int u = 0; u < 2; u++) {
                int idx = tid + u * 256;
                int row = idx >> 2, c = idx & 3;
                cpasync16(db + row * 64 + ((c ^ ((row >> 1) & 3)) << 4),
                          src + (size_t)(rb + row) * K + kofs + c * 8);
            }
        }
    };

    stage(0);
    asm volatile("cp.async.commit_group;" ::: "memory");

    for (int i = 0; i < nch; i++) {
        if (i + 1 < nch) {
            stage(i + 1);
            asm volatile("cp.async.commit_group;" ::: "memory");
            asm volatile("cp.async.wait_group 1;" ::: "memory");
        } else {
            asm volatile("cp.async.wait_group 0;" ::: "memory");
        }
        __syncthreads();

        const uint32_t buf = sbase + (i & 1) * 32768;
#pragma unroll
        for (int p = 0; p < 3; p++) {
            const uint32_t ab = buf + (p == 1 ? 8192 : 0);
            const uint32_t bb = buf + (p == 2 ? 24576 : 16384);
#pragma unroll
            for (int kk = 0; kk < 2; kk++) {
                uint32_t af[4][4], bf[4][2];
#pragma unroll
                for (int t = 0; t < 4; t++)
                    ldm_x4(af[t], ab + a_off[t] + (((kk * 2 + a_half) ^ a_sw[t]) << 4));
#pragma unroll
                for (int t = 0; t < 4; t++)
                    ldm_x2(bf[t], bb + b_off[t] + (((kk * 2 + b_half) ^ b_sw[t]) << 4));
#pragma unroll
                for (int ti = 0; ti < 4; ti++)
#pragma unroll
                    for (int tj = 0; tj < 4; tj++)
                        mma_bf16(acc[ti][tj], af[ti], bf[tj]);
            }
        }
        __syncthreads();
    }

#pragma unroll
    for (int i = 0; i < 4; i++) {
#pragma unroll
        for (int half = 0; half < 2; half++) {
            const int row = m0 + wm + i * 16 + (lane >> 2) + half * 8;
#pragma unroll
            for (int j = 0; j < 4; j++) {
                const int col = n0 + wn + j * 8 + (lane & 3) * 2;
                float2 bv = *reinterpret_cast<const float2*>(bias + col);
                float v0 = acc[i][j][half * 2 + 0] + bv.x;
                float v1 = acc[i][j][half * 2 + 1] + bv.y;
                if (EPI == EP_EMBED || EPI == EP_RES) {
                    const int er = (EPI == EP_EMBED) ? (row & (LSEQ - 1)) : row;
                    float2 ev = *reinterpret_cast<const float2*>(extra + (size_t)er * N + col);
                    v0 += ev.x; v1 += ev.y;
                }
                if (EPI == EP_GELU) {
                    v0 = 0.5f * v0 * (1.f + erff(v0 * 0.70710678118654752f));
                    v1 = 0.5f * v1 * (1.f + erff(v1 * 0.70710678118654752f));
                }
                if (EPI == EP_GELU || EPI == EP_SPLIT) {
                    __nv_bfloat16 h0, l0, h1, l1;
                    split2(v0, h0, l0); split2(v1, h1, l1);
                    *reinterpret_cast<uint32_t*>(Chi + (size_t)row * N + col) = pack2(h0, h1);
                    *reinterpret_cast<uint32_t*>(Clo + (size_t)row * N + col) = pack2(l0, l1);
                } else {
                    *reinterpret_cast<float2*>(Cf + (size_t)row * N + col) = make_float2(v0, v1);
                }
            }
        }
    }
}

// ---- LayerNorm ----
template <bool WF32, bool WSPLIT>
__global__ __launch_bounds__(256)
void ln_kernel(const float* __restrict__ x, const float* __restrict__ w,
               const float* __restrict__ b, float* __restrict__ y,
               __nv_bfloat16* __restrict__ yhi, __nv_bfloat16* __restrict__ ylo)
{
    const int row = blockIdx.x, c = threadIdx.x * 4;
    float4 v = *reinterpret_cast<const float4*>(x + (size_t)row * DMODEL + c);
    float s = v.x + v.y + v.z + v.w;
    float sq = v.x*v.x + v.y*v.y + v.z*v.z + v.w*v.w;
#pragma unroll
    for (int o = 16; o; o >>= 1) {
        s += __shfl_xor_sync(~0u, s, o); sq += __shfl_xor_sync(~0u, sq, o);
    }
    __shared__ float ss[8], ssq[8];
    const int warp = threadIdx.x >> 5, lane = threadIdx.x & 31;
    if (lane == 0) { ss[warp] = s; ssq[warp] = sq; }
    __syncthreads();
    float tot = 0.f, totq = 0.f;
#pragma unroll
    for (int i = 0; i < 8; i++) { tot += ss[i]; totq += ssq[i]; }
    const float mu = tot / DMODEL, var = totq / DMODEL - mu * mu;
    const float inv = rsqrtf(var + LN_EPS);
    float4 wv = *reinterpret_cast<const float4*>(w + c);
    float4 bv = *reinterpret_cast<const float4*>(b + c);
    float4 o;
    o.x = (v.x-mu)*inv*wv.x + bv.x; o.y = (v.y-mu)*inv*wv.y + bv.y;
    o.z = (v.z-mu)*inv*wv.z + bv.z; o.w = (v.w-mu)*inv*wv.w + bv.w;
    if (WF32) *reinterpret_cast<float4*>(y + (size_t)row * DMODEL + c) = o;
    if (WSPLIT) {
        __nv_bfloat16 h0,l0,h1,l1,h2,l2,h3,l3;
        split2(o.x,h0,l0); split2(o.y,h1,l1); split2(o.z,h2,l2); split2(o.w,h3,l3);
        *reinterpret_cast<uint2*>(yhi + (size_t)row*DMODEL + c) = make_uint2(pack2(h0,h1), pack2(h2,h3));
        *reinterpret_cast<uint2*>(ylo + (size_t)row*DMODEL + c) = make_uint2(pack2(l0,l1), pack2(l2,l3));
    }
}

// ---- HMMA flash attention (causal), split-3 bf16 ----
// grid (L/128, B*H), 256 threads; Q tile 128 rows (16/warp), kv tiles of 64.
// smem: Qhi 16K | Qlo 16K | 2 x [Khi 8K | Klo 8K | Vhi 8K | Vlo 8K]
#define FA_SMEM (32768 + 2*32768)

__global__ __launch_bounds__(256, 1)
void fa_kernel(const __nv_bfloat16* __restrict__ kqhi, const __nv_bfloat16* __restrict__ kqlo,
               const __nv_bfloat16* __restrict__ vhi,  const __nv_bfloat16* __restrict__ vlo,
               __nv_bfloat16* __restrict__ ohi, __nv_bfloat16* __restrict__ olo)
{
    extern __shared__ char dsm[];
    const uint32_t sb = smem_u32(dsm);
    const int tid = threadIdx.x, w = tid >> 5, lane = tid & 31;
    const int qt = blockIdx.x, bh = blockIdx.y;
    const int bidx = bh >> 4, h = bh & 15;
    const int rowbase = bidx * LSEQ;
    const int q0 = qt * 128;
    const int jmax = 2 * qt + 1;

    // stage Q (hi/lo) 128x64
#pragma unroll
    for (int t = 0; t < 8; t++) {
        const int arr = t >> 2;
        const int row = ((t & 3) * 256 + tid) >> 3;
        const int ch = tid & 7;
        const __nv_bfloat16* base = arr ? kqlo : kqhi;
        cpasync16(sb + arr * 16384 + row * 128 + ((ch ^ (row & 7)) << 4),
                  base + (size_t)(rowbase + q0 + row) * (2 * DMODEL) + DMODEL + h * HD + ch * 8);
    }
    // stage KV tile jt into buffer b
    auto stageKV = [&](int jt, int b) {
        const uint32_t buf = sb + 32768 + b * 32768;
        const int n0 = jt * 64;
#pragma unroll
        for (int t = 0; t < 8; t++) {
            const int arr = t >> 1;   // 0 Khi 1 Klo 2 Vhi 3 Vlo
            const int row = ((t & 1) * 256 + tid) >> 3;
            const int ch = tid & 7;
            const __nv_bfloat16* base = (arr == 0) ? kqhi : (arr == 1) ? kqlo
                                      : (arr == 2) ? vhi : vlo;
            const size_t stride = (arr < 2) ? (2 * DMODEL) : DMODEL;
            cpasync16(buf + arr * 8192 + row * 128 + ((ch ^ (row & 7)) << 4),
                      base + (size_t)(rowbase + n0 + row) * stride + h * HD + ch * 8);
        }
    };
    stageKV(0, 0);
    asm volatile("cp.async.commit_group;" ::: "memory");

    // per-warp state
    const int r0 = q0 + w * 16 + (lane >> 2);
    float m0 = -INFINITY, m1 = -INFINITY, l0 = 0.f, l1 = 0.f;
    float o[8][4];
#pragma unroll
    for (int j = 0; j < 8; j++)
#pragma unroll
        for (int c = 0; c < 4; c++) o[j][c] = 0.f;

    uint32_t qh[4][4], ql[4][4];
    const int qrow = w * 16 + (lane & 7) + ((lane >> 3) & 1) * 8;
    const uint32_t qhalf = lane >> 4;

    for (int jt = 0; jt <= jmax; jt++) {
        if (jt < jmax) {
            stageKV(jt + 1, (jt + 1) & 1);
            asm volatile("cp.async.commit_group;" ::: "memory");
            asm volatile("cp.async.wait_group 1;" ::: "memory");
        } else {
            asm volatile("cp.async.wait_group 0;" ::: "memory");
        }
        __syncthreads();

        if (jt == 0) {
#pragma unroll
            for (int kc = 0; kc < 4; kc++) {
                const uint32_t co = (((kc * 2 + qhalf) ^ (qrow & 7)) << 4);
                ldm_x4(qh[kc], sb + qrow * 128 + co);
                ldm_x4(ql[kc], sb + 16384 + qrow * 128 + co);
            }
        }

        const uint32_t buf = sb + 32768 + (jt & 1) * 32768;
        const int n0 = jt * 64;

        // S = QK^T (split-3)
        float s[8][4];
#pragma unroll
        for (int j = 0; j < 8; j++) {
            s[j][0] = s[j][1] = s[j][2] = s[j][3] = 0.f;
            const int krow = j * 8 + (lane & 7);
            const uint32_t khalf = (lane >> 3) & 1;
#pragma unroll
            for (int kc = 0; kc < 4; kc++) {
                const uint32_t co = krow * 128 + (((kc * 2 + khalf) ^ (krow & 7)) << 4);
                uint32_t kh[2], kl[2];
                ldm_x2(kh, buf + co);
                ldm_x2(kl, buf + 8192 + co);
                mma_bf16(s[j], qh[kc], kh);
                mma_bf16(s[j], ql[kc], kh);
                mma_bf16(s[j], qh[kc], kl);
            }
        }
        // scale + causal mask
#pragma unroll
        for (int j = 0; j < 8; j++) {
            s[j][0] *= 0.125f; s[j][1] *= 0.125f; s[j][2] *= 0.125f; s[j][3] *= 0.125f;
        }
        if (n0 + 63 > q0 + w * 16) {
#pragma unroll
            for (int j = 0; j < 8; j++) {
                const int c0 = n0 + j * 8 + (lane & 3) * 2;
                if (c0 > r0)     s[j][0] = -INFINITY;
                if (c0 + 1 > r0) s[j][1] = -INFINITY;
                if (c0 > r0 + 8)     s[j][2] = -INFINITY;
                if (c0 + 1 > r0 + 8) s[j][3] = -INFINITY;
            }
        }
        // online softmax
        float mx0 = -INFINITY, mx1 = -INFINITY;
#pragma unroll
        for (int j = 0; j < 8; j++) {
            mx0 = fmaxf(mx0, fmaxf(s[j][0], s[j][1]));
            mx1 = fmaxf(mx1, fmaxf(s[j][2], s[j][3]));
        }
        mx0 = fmaxf(mx0, __shfl_xor_sync(~0u, mx0, 1));
        mx0 = fmaxf(mx0, __shfl_xor_sync(~0u, mx0, 2));
        mx1 = fmaxf(mx1, __shfl_xor_sync(~0u, mx1, 1));
        mx1 = fmaxf(mx1, __shfl_xor_sync(~0u, mx1, 2));
        const float nm0 = fmaxf(m0, mx0), nm1 = fmaxf(m1, mx1);
        const float cr0 = __expf(m0 - nm0), cr1 = __expf(m1 - nm1);
        float rs0 = 0.f, rs1 = 0.f;
#pragma unroll
        for (int j = 0; j < 8; j++) {
            s[j][0] = __expf(s[j][0] - nm0); rs0 += s[j][0];
            s[j][1] = __expf(s[j][1] - nm0); rs0 += s[j][1];
            s[j][2] = __expf(s[j][2] - nm1); rs1 += s[j][2];
            s[j][3] = __expf(s[j][3] - nm1); rs1 += s[j][3];
        }
        rs0 += __shfl_xor_sync(~0u, rs0, 1); rs0 += __shfl_xor_sync(~0u, rs0, 2);
        rs1 += __shfl_xor_sync(~0u, rs1, 1); rs1 += __shfl_xor_sync(~0u, rs1, 2);
        l0 = l0 * cr0 + rs0; l1 = l1 * cr1 + rs1;
        m0 = nm0; m1 = nm1;
#pragma unroll
        for (int j = 0; j < 8; j++) {
            o[j][0] *= cr0; o[j][1] *= cr0; o[j][2] *= cr1; o[j][3] *= cr1;
        }
        // P fragments (split)
        uint32_t ph[4][4], pl[4][4];
#pragma unroll
        for (int kc = 0; kc < 4; kc++) {
#pragma unroll
            for (int half = 0; half < 2; half++) {
                const int t2 = 2 * kc + half;
                __nv_bfloat16 a0, b0, a1, b1;
                split2(s[t2][0], a0, b0); split2(s[t2][1], a1, b1);
                ph[kc][half * 2 + 0] = pack2(a0, a1);
                pl[kc][half * 2 + 0] = pack2(b0, b1);
                split2(s[t2][2], a0, b0); split2(s[t2][3], a1, b1);
                ph[kc][half * 2 + 1] = pack2(a0, a1);
                pl[kc][half * 2 + 1] = pack2(b0, b1);
            }
        }
        // wait: ph reg order is {a0(klow,g0), a1(klow,g1), a2(khigh,g0), a3(khigh,g1)}
        // above fills [0],[1] for half=0 and overwrites for half=1 -> fix indexing:
        // (handled by writing half*2+0 / half*2+1)
        // O += P @ V (split-3)
#pragma unroll
        for (int j2 = 0; j2 < 8; j2++) {
#pragma unroll
            for (int kc = 0; kc < 4; kc++) {
                const int vrow = kc * 16 + (lane & 15);
                const uint32_t co = vrow * 128 + ((j2 ^ (vrow & 7)) << 4);
                uint32_t vh[2], vl[2];
                ldm_x2t(vh, buf + 16384 + co);
                ldm_x2t(vl, buf + 24576 + co);
                mma_bf16(o[j2], ph[kc], vh);
                mma_bf16(o[j2], pl[kc], vh);
                mma_bf16(o[j2], ph[kc], vl);
            }
        }
        __syncthreads();
    }

    const float il0 = 1.f / l0, il1 = 1.f / l1;
#pragma unroll
    for (int j2 = 0; j2 < 8; j2++) {
        const int col = h * HD + j2 * 8 + (lane & 3) * 2;
        float v0 = o[j2][0] * il0, v1 = o[j2][1] * il0;
        float v2 = o[j2][2] * il1, v3 = o[j2][3] * il1;
        __nv_bfloat16 h0, e0, h1, e1;
        split2(v0, h0, e0); split2(v1, h1, e1);
        *reinterpret_cast<uint32_t*>(ohi + (size_t)(rowbase + r0) * DMODEL + col) = pack2(h0, h1);
        *reinterpret_cast<uint32_t*>(olo + (size_t)(rowbase + r0) * DMODEL + col) = pack2(e0, e1);
        split2(v2, h0, e0); split2(v3, h1, e1);
        *reinterpret_cast<uint32_t*>(ohi + (size_t)(rowbase + r0 + 8) * DMODEL + col) = pack2(h0, h1);
        *reinterpret_cast<uint32_t*>(olo + (size_t)(rowbase + r0 + 8) * DMODEL + col) = pack2(e0, e1);
    }
}

extern "C" void kernel_launch(void* const* d_in, const int* in_sizes, int n_in,
                              void* d_out, int out_size)
{
    const float* x      = (const float*)d_in[0];
    const float* wte_w  = (const float*)d_in[1];
    const float* wte_b  = (const float*)d_in[2];
    const float* wpe    = (const float*)d_in[3];
    const float* ln1_w  = (const float*)d_in[4];
    const float* ln1_b  = (const float*)d_in[5];
    const float* kq_w   = (const float*)d_in[6];
    const float* kq_b   = (const float*)d_in[7];
    const float* v_w    = (const float*)d_in[8];
    const float* v_b    = (const float*)d_in[9];
    const float* ao_w   = (const float*)d_in[10];
    const float* ao_b   = (const float*)d_in[11];
    const float* ln2_w  = (const float*)d_in[12];
    const float* ln2_b  = (const float*)d_in[13];
    const float* fc_w   = (const float*)d_in[14];
    const float* fc_b   = (const float*)d_in[15];
    const float* proj_w = (const float*)d_in[16];
    const float* proj_b = (const float*)d_in[17];

    float *h, *hn;
    cudaGetSymbolAddress((void**)&h, g_h);
    cudaGetSymbolAddress((void**)&hn, g_hn);
    __nv_bfloat16 *xhi,*xlo,*hnhi,*hnlo,*kqhi,*kqlo,*vhi,*vlo,*ohi,*olo,*xohi,*xolo,*mlhi,*mllo;
    __nv_bfloat16 *wtehi,*wtelo,*kqwhi,*kqwlo,*vwhi,*vwlo,*aowhi,*aowlo,*fcwhi,*fcwlo,*pjwhi,*pjwlo;
    cudaGetSymbolAddress((void**)&xhi, g_x_hi);   cudaGetSymbolAddress((void**)&xlo, g_x_lo);
    cudaGetSymbolAddress((void**)&hnhi, g_hn_hi); cudaGetSymbolAddress((void**)&hnlo, g_hn_lo);
    cudaGetSymbolAddress((void**)&kqhi, g_kq_hi); cudaGetSymbolAddress((void**)&kqlo, g_kq_lo);
    cudaGetSymbolAddress((void**)&vhi, g_v_hi);   cudaGetSymbolAddress((void**)&vlo, g_v_lo);
    cudaGetSymbolAddress((void**)&ohi, g_o_hi);   cudaGetSymbolAddress((void**)&olo, g_o_lo);
    cudaGetSymbolAddress((void**)&xohi, g_xo_hi); cudaGetSymbolAddress((void**)&xolo, g_xo_lo);
    cudaGetSymbolAddress((void**)&mlhi, g_ml_hi); cudaGetSymbolAddress((void**)&mllo, g_ml_lo);
    cudaGetSymbolAddress((void**)&wtehi, g_wte_hi); cudaGetSymbolAddress((void**)&wtelo, g_wte_lo);
    cudaGetSymbolAddress((void**)&kqwhi, g_kqw_hi); cudaGetSymbolAddress((void**)&kqwlo, g_kqw_lo);
    cudaGetSymbolAddress((void**)&vwhi, g_vw_hi);   cudaGetSymbolAddress((void**)&vwlo, g_vw_lo);
    cudaGetSymbolAddress((void**)&aowhi, g_aow_hi); cudaGetSymbolAddress((void**)&aowlo, g_aow_lo);
    cudaGetSymbolAddress((void**)&fcwhi, g_fcw_hi); cudaGetSymbolAddress((void**)&fcwlo, g_fcw_lo);
    cudaGetSymbolAddress((void**)&pjwhi, g_pjw_hi); cudaGetSymbolAddress((void**)&pjwlo, g_pjw_lo);

    float* out0     = (float*)d_out;
    float* attn_out = out0 + (size_t)NTOK * INPUT_DIM;

    cudaFuncSetAttribute(hmma_gemm<EP_EMBED>, cudaFuncAttributeMaxDynamicSharedMemorySize, HM_SMEM);
    cudaFuncSetAttribute(hmma_gemm<EP_BIAS>,  cudaFuncAttributeMaxDynamicSharedMemorySize, HM_SMEM);
    cudaFuncSetAttribute(hmma_gemm<EP_RES>,   cudaFuncAttributeMaxDynamicSharedMemorySize, HM_SMEM);
    cudaFuncSetAttribute(hmma_gemm<EP_GELU>,  cudaFuncAttributeMaxDynamicSharedMemorySize, HM_SMEM);
    cudaFuncSetAttribute(hmma_gemm<EP_SPLIT>, cudaFuncAttributeMaxDynamicSharedMemorySize, HM_SMEM);
    cudaFuncSetAttribute(fa_kernel, cudaFuncAttributeMaxDynamicSharedMemorySize, FA_SMEM);

    dim3 wsb(32, 8);
    xsplit_kernel<<<(NTOK*INPUT_DIM)/256, 256>>>(x, xhi, xlo, NTOK*INPUT_DIM);
    wsplit_kernel<<<dim3(DMODEL/32, INPUT_DIM/32), wsb>>>(wte_w, INPUT_DIM, DMODEL, wtehi, wtelo);
    wsplit_kernel<<<dim3(2*DMODEL/32, DMODEL/32), wsb>>>(kq_w, DMODEL, 2*DMODEL, kqwhi, kqwlo);
    wsplit_kernel<<<dim3(DMODEL/32, DMODEL/32), wsb>>>(v_w, DMODEL, DMODEL, vwhi, vwlo);
    wsplit_kernel<<<dim3(DMODEL/32, DMODEL/32), wsb>>>(ao_w, DMODEL, DMODEL, aowhi, aowlo);
    wsplit_kernel<<<dim3(MLPH/32, DMODEL/32), wsb>>>(fc_w, DMODEL, MLPH, fcwhi, fcwlo);
    wsplit_kernel<<<dim3(INPUT_DIM/32, MLPH/32), wsb>>>(proj_w, MLPH, INPUT_DIM, pjwhi, pjwlo);

    hmma_gemm<EP_EMBED><<<dim3(DMODEL/128, NTOK/128), 256, HM_SMEM>>>(
        NTOK, DMODEL, INPUT_DIM, xhi, xlo, wtehi, wtelo, wte_b, wpe, h, nullptr, nullptr);
    ln_kernel<true, true><<<NTOK, 256>>>(h, ln1_w, ln1_b, hn, hnhi, hnlo);
    hmma_gemm<EP_SPLIT><<<dim3(2*DMODEL/128, NTOK/128), 256, HM_SMEM>>>(
        NTOK, 2*DMODEL, DMODEL, hnhi, hnlo, kqwhi, kqwlo, kq_b, nullptr, nullptr, kqhi, kqlo);
    hmma_gemm<EP_SPLIT><<<dim3(DMODEL/128, NTOK/128), 256, HM_SMEM>>>(
        NTOK, DMODEL, DMODEL, hnhi, hnlo, vwhi, vwlo, v_b, nullptr, nullptr, vhi, vlo);
    fa_kernel<<<dim3(LSEQ/128, BATCH*NHEAD), 256, FA_SMEM>>>(kqhi, kqlo, vhi, vlo, ohi, olo);
    hmma_gemm<EP_RES><<<dim3(DMODEL/128, NTOK/128), 256, HM_SMEM>>>(
        NTOK, DMODEL, DMODEL, ohi, olo, aowhi, aowlo, ao_b, hn, attn_out, nullptr, nullptr);
    ln_kernel<false, true><<<NTOK, 256>>>(attn_out, ln2_w, ln2_b, nullptr, xohi, xolo);
    hmma_gemm<EP_GELU><<<dim3(MLPH/128, NTOK/128), 256, HM_SMEM>>>(
        NTOK, MLPH, DMODEL, xohi, xolo, fcwhi, fcwlo, fc_b, nullptr, nullptr, mlhi, mllo);
    hmma_gemm<EP_BIAS><<<dim3(INPUT_DIM/128, NTOK/128), 256, HM_SMEM>>>(
        NTOK, INPUT_DIM, MLPH, mlhi, mllo, pjwhi, pjwlo, proj_b, nullptr, out0, nullptr, nullptr);
}